// round 3
// baseline (speedup 1.0000x reference)
#include <cuda_runtime.h>
#include <math.h>

#define NMAX  12288
#define SEG   1536           // NMAX / NSEG
#define NSEG  8
#define QB    128            // threads per NN block = queries per block
#define QBLK  (SEG / QB)     // 12 query blocks per segment
#define EPT   (SEG / QB)     // 12 elements per thread in the segment scan

struct CMat { float m[9]; float s; };

// ---- persistent scratch (zero-initialized at module load; re-armed each replay) ----
__device__ unsigned long long g_best[NMAX];   // stores ~((ord(d)<<32)|orig_j); 0 = armed
__device__ double g_blk_sum[64];
__device__ int    g_blk_cnt[64];
__device__ int    g_done = 0;

// monotone float -> uint mapping (order-preserving, invertible)
__device__ __forceinline__ unsigned int ford(float f) {
    unsigned int u = __float_as_uint(f);
    return (u & 0x80000000u) ? ~u : (u | 0x80000000u);
}
__device__ __forceinline__ float finv(unsigned int o) {
    unsigned int u = (o & 0x80000000u) ? (o ^ 0x80000000u) : ~o;
    return __uint_as_float(u);
}

// ============================================================
// Kernel 1: fused compaction + NN search.
// grid = (NSEG*QBLK, NSEG); block = QB threads.
// d_eff = sq_j - 2 w_i.w_j (query constant sq_i dropped; added back in strain)
// ============================================================
__global__ void __launch_bounds__(QB) k_nn(const float* __restrict__ new_xyz,
                                           const float* __restrict__ gt_sdf) {
    __shared__ float4 tile[SEG];
    __shared__ int    s_cor[SEG];     // candidate compact slot -> original index
    __shared__ int    s_qorig[QB];    // query window slot -> original index (csp != qseg path)
    __shared__ int    s_w[4];         // per-warp scan totals
    __shared__ int    s_cntq;

    int tid = threadIdx.x, lane = tid & 31, wid = tid >> 5;
    int qb  = blockIdx.x, csp = blockIdx.y;
    int qseg = qb / QBLK, qb_in = qb % QBLK;
    int qw0  = qb_in * QB;

    // ---------- query-segment scan (flags only; build window mapping) ----------
    {
        int s0 = qseg * SEG;
        const float4* ps = (const float4*)(gt_sdf + s0 + EPT * tid);
        float4 a = ps[0], b = ps[1], c = ps[2];
        float v[12] = {a.x,a.y,a.z,a.w, b.x,b.y,b.z,b.w, c.x,c.y,c.z,c.w};
        unsigned fl = 0; int myc = 0;
        #pragma unroll
        for (int e = 0; e < 12; ++e) if (v[e] < 1e-8f) { fl |= 1u << e; myc++; }
        int pre = myc;
        #pragma unroll
        for (int o = 1; o < 32; o <<= 1) { int t2 = __shfl_up_sync(~0u, pre, o); if (lane >= o) pre += t2; }
        if (lane == 31) s_w[wid] = pre;
        __syncthreads();
        int woff = 0;
        #pragma unroll
        for (int w = 0; w < 4; ++w) if (w < wid) woff += s_w[w];
        int pos = woff + pre - myc;                         // exclusive global prefix
        if (tid == 0) s_cntq = s_w[0] + s_w[1] + s_w[2] + s_w[3];
        if (csp != qseg) {
            #pragma unroll
            for (int e = 0; e < 12; ++e) {
                if (fl & (1u << e)) {
                    if (pos >= qw0 && pos < qw0 + QB) s_qorig[pos - qw0] = s0 + EPT * tid + e;
                    pos++;
                }
            }
        }
    }
    __syncthreads();
    int cntq = s_cntq;
    bool active = (qw0 < cntq);                             // block-uniform

    if (active) {
        // ---------- candidate-segment scan (compact into smem tile) ----------
        int cntc;
        {
            int s0 = csp * SEG;
            const float4* ps = (const float4*)(gt_sdf + s0 + EPT * tid);
            float4 a = ps[0], b = ps[1], c = ps[2];
            float v[12] = {a.x,a.y,a.z,a.w, b.x,b.y,b.z,b.w, c.x,c.y,c.z,c.w};
            unsigned fl = 0; int myc = 0;
            #pragma unroll
            for (int e = 0; e < 12; ++e) if (v[e] < 1e-8f) { fl |= 1u << e; myc++; }
            int pre = myc;
            #pragma unroll
            for (int o = 1; o < 32; o <<= 1) { int t2 = __shfl_up_sync(~0u, pre, o); if (lane >= o) pre += t2; }
            if (lane == 31) s_w[wid] = pre;
            __syncthreads();
            int woff = 0;
            #pragma unroll
            for (int w = 0; w < 4; ++w) if (w < wid) woff += s_w[w];
            int pos = woff + pre - myc;
            cntc = s_w[0] + s_w[1] + s_w[2] + s_w[3];
            #pragma unroll
            for (int e = 0; e < 12; ++e) {
                if (fl & (1u << e)) {
                    int idx = s0 + EPT * tid + e;
                    float x = new_xyz[3 * idx + 0];
                    float y = new_xyz[3 * idx + 1];
                    float z = new_xyz[3 * idx + 2];
                    tile[pos]  = make_float4(x, y, z, x * x + y * y + z * z);
                    s_cor[pos] = idx;
                    pos++;
                }
            }
        }
        __syncthreads();

        // ---------- per-thread query ----------
        int  ql = qw0 + tid;                                // compact slot within qseg
        bool qa = (ql < cntq) && (cntc > 0);
        int  qorig = 0;
        if (qa) qorig = (csp == qseg) ? s_cor[ql] : s_qorig[tid];
        float qx = new_xyz[3 * qorig + 0];
        float qy = new_xyz[3 * qorig + 1];
        float qz = new_xyz[3 * qorig + 2];
        float ax = -2.f * qx, ay = -2.f * qy, az = -2.f * qz;
        float best = 3.0e38f;
        int   bc   = 0;

        if (csp != qseg) {
            #pragma unroll 8
            for (int k = 0; k < cntc; ++k) {
                float4 c = tile[k];
                float d = fmaf(c.x, ax, fmaf(c.y, ay, fmaf(c.z, az, c.w)));
                if (d < best) { best = d; bc = k; }
            }
        } else {
            int sk = ql;                                    // self slot in own segment
            #pragma unroll 8
            for (int k = 0; k < cntc; ++k) {
                float4 c = tile[k];
                float d = fmaf(c.x, ax, fmaf(c.y, ay, fmaf(c.z, az, c.w)));
                if (d < best && k != sk) { best = d; bc = k; }
            }
        }

        if (qa) {
            unsigned long long key =
                ((unsigned long long)ford(best) << 32) | (unsigned int)s_cor[bc];
            atomicMax(&g_best[qorig], ~key);                // max(~key) == min(key)
        }
    }
}

// ============================================================
// Kernel 2: strain + full reduction (last-block), re-arms g_best.
// grid = NMAX/256 = 48 blocks x 256 threads.
// ============================================================
__global__ void __launch_bounds__(256) k_strain(const float* __restrict__ new_xyz,
                                                const float* __restrict__ xyz,
                                                const float* __restrict__ gt_sdf,
                                                CMat C, float* __restrict__ out,
                                                int nblocks) {
    __shared__ double s_sum[256];
    __shared__ int    s_cnt[256];
    __shared__ int    s_last;
    int t = threadIdx.x;
    int i = blockIdx.x * 256 + t;                           // original index

    double qsq = 0.0;
    int cnt = 0;
    unsigned long long kp = g_best[i];
    g_best[i] = 0ULL;                                       // re-arm for next replay
    if (kp != 0ULL && gt_sdf[i] < 1e-8f) {
        unsigned long long key = ~kp;
        float deff = finv((unsigned int)(key >> 32));
        int   nn   = (int)(unsigned int)(key & 0xffffffffu);
        float wqx = new_xyz[3 * i + 0], wqy = new_xyz[3 * i + 1], wqz = new_xyz[3 * i + 2];
        float sqi = wqx * wqx + wqy * wqy + wqz * wqz;
        float mind2 = deff + sqi;                           // add back sq_i
        if (mind2 > 1e-16f) {                               // inside & (nn_d > 1e-8)
            cnt = 1;
            float wnx = new_xyz[3 * nn + 0], wny = new_xyz[3 * nn + 1], wnz = new_xyz[3 * nn + 2];
            float xi0 = xyz[3 * i + 0],  xi1 = xyz[3 * i + 1],  xi2 = xyz[3 * i + 2];
            float xn0 = xyz[3 * nn + 0], xn1 = xyz[3 * nn + 1], xn2 = xyz[3 * nn + 2];
            float du = (wnx - xn0) - (wqx - xi0);           // dm = motion[nn] - motion[i]
            float dv = (wny - xn1) - (wqy - xi1);
            float dw = (wnz - xn2) - (wqz - xi2);
            float dx = wnx - wqx + 1e-8f;
            float dy = wny - wqy + 1e-8f;
            float dz = wnz - wqz + 1e-8f;
            float e0 = du / dx, e1 = dv / dy, e2 = dw / dz;
            float e3 = (du / dy + dv / dx) * 0.5f;
            float e4 = (du / dz + dw / dx) * 0.5f;
            float e5 = (dw / dy + dv / dz) * 0.5f;
            float r0 = C.m[0] * e0 + C.m[1] * e1 + C.m[2] * e2;
            float r1 = C.m[3] * e0 + C.m[4] * e1 + C.m[5] * e2;
            float r2 = C.m[6] * e0 + C.m[7] * e1 + C.m[8] * e2;
            float q  = e0 * r0 + e1 * r1 + e2 * r2
                     + C.s * (e3 * e3 + e4 * e4 + e5 * e5);
            qsq = (double)q * (double)q;
        }
    }
    s_sum[t] = qsq;
    s_cnt[t] = cnt;
    __syncthreads();
    #pragma unroll
    for (int o = 128; o > 0; o >>= 1) {                     // deterministic tree
        if (t < o) { s_sum[t] += s_sum[t + o]; s_cnt[t] += s_cnt[t + o]; }
        __syncthreads();
    }
    if (t == 0) {
        g_blk_sum[blockIdx.x] = s_sum[0];
        g_blk_cnt[blockIdx.x] = s_cnt[0];
        __threadfence();
        int v = atomicAdd(&g_done, 1);
        s_last = (v == nblocks - 1);
    }
    __syncthreads();

    if (s_last) {                                           // last block: fixed-order final
        __threadfence();
        double s = 0.0; int c = 0;
        if (t < 64)
            for (int b = t; b < nblocks; b += 64) { s += g_blk_sum[b]; c += g_blk_cnt[b]; }
        s_sum[t] = s; s_cnt[t] = c;
        __syncthreads();
        #pragma unroll
        for (int o = 32; o > 0; o >>= 1) {
            if (t < o) { s_sum[t] += s_sum[t + o]; s_cnt[t] += s_cnt[t + o]; }
            __syncthreads();
        }
        if (t == 0) {
            out[0] = (float)(sqrt(s_sum[0]) / (double)s_cnt[0]);
            g_done = 0;                                     // reset for next replay
        }
    }
}

// ============================================================
extern "C" void kernel_launch(void* const* d_in, const int* in_sizes, int n_in,
                              void* d_out, int out_size) {
    const float* new_xyz = (const float*)d_in[0];
    const float* xyz     = (const float*)d_in[1];
    const float* gt_sdf  = (const float*)d_in[2];

    CMat C;
    {
        const double EP = 0.21, VP = 0.4;
        double A[3][3] = {{1.0/EP, -VP/EP, -VP/EP},
                          {-VP/EP, 1.0/EP, -VP/EP},
                          {-VP,    -VP,    1.0/EP}};
        double det = A[0][0]*(A[1][1]*A[2][2]-A[1][2]*A[2][1])
                   - A[0][1]*(A[1][0]*A[2][2]-A[1][2]*A[2][0])
                   + A[0][2]*(A[1][0]*A[2][1]-A[1][1]*A[2][0]);
        double inv[3][3];
        inv[0][0] = (A[1][1]*A[2][2]-A[1][2]*A[2][1])/det;
        inv[0][1] = (A[0][2]*A[2][1]-A[0][1]*A[2][2])/det;
        inv[0][2] = (A[0][1]*A[1][2]-A[0][2]*A[1][1])/det;
        inv[1][0] = (A[1][2]*A[2][0]-A[1][0]*A[2][2])/det;
        inv[1][1] = (A[0][0]*A[2][2]-A[0][2]*A[2][0])/det;
        inv[1][2] = (A[0][2]*A[1][0]-A[0][0]*A[1][2])/det;
        inv[2][0] = (A[1][0]*A[2][1]-A[1][1]*A[2][0])/det;
        inv[2][1] = (A[0][1]*A[2][0]-A[0][0]*A[2][1])/det;
        inv[2][2] = (A[0][0]*A[1][1]-A[0][1]*A[1][0])/det;
        for (int i = 0; i < 3; i++)
            for (int j = 0; j < 3; j++)
                C.m[i * 3 + j] = (float)inv[i][j];
        C.s = (float)(EP / (2.0 * (1.0 + VP)));
    }

    dim3 g1(NSEG * QBLK, NSEG);                             // (96, 8)
    k_nn<<<g1, QB>>>(new_xyz, gt_sdf);
    int nb = NMAX / 256;                                    // 48
    k_strain<<<nb, 256>>>(new_xyz, xyz, gt_sdf, C, (float*)d_out, nb);
}